// round 8
// baseline (speedup 1.0000x reference)
#include <cuda_runtime.h>
#include <math.h>

#define NN 100000
#define EE 1600000

// ---------------- scratch (static device globals; no allocations) -------------
__device__ float4 g_x4[(size_t)NN * 32];   // 100000 x 128 floats (activations)
__device__ float4 g_h4[(size_t)NN * 32];   // gemm output / gather input
__device__ int    g_indeg[NN];
__device__ int    g_outdeg[NN];
__device__ float  g_nsrc[NN];
__device__ float  g_ndst[NN];
__device__ int    g_rowstart[NN + 1];
__device__ int    g_cursor[NN];
__device__ int    g_col[EE];
__device__ int    g_bsums[128];
__device__ int    g_is64;                  // 1 if edge_index buffer is int64

// Edge accessor: idx in [0, 2*EE). Works for int32 and little-endian int64 buffers.
__device__ __forceinline__ int edge_at(const int* __restrict__ w, int is64, size_t idx) {
    return is64 ? w[idx << 1] : w[idx];
}

// ---------------- dtype detect ------------------------------------------------
__global__ void detect_kernel(const int* __restrict__ w) {
    // One block, 128 threads. int64 (values < 2^31) => every odd 32-bit word is 0.
    __shared__ int nz;
    if (threadIdx.x == 0) nz = 0;
    __syncthreads();
    int v = w[2 * threadIdx.x + 1];
    if (v != 0) atomicAdd(&nz, 1);
    __syncthreads();
    if (threadIdx.x == 0) g_is64 = (nz == 0) ? 1 : 0;
}

// ---------------- degree / norms --------------------------------------------
__global__ void zero_kernel() {
    int i = blockIdx.x * blockDim.x + threadIdx.x;
    if (i < NN) {
        g_indeg[i] = 0;
        g_outdeg[i] = 0;
        g_cursor[i] = 0;
    }
}

__global__ void degree_kernel(const int* __restrict__ ei) {
    int i = blockIdx.x * blockDim.x + threadIdx.x;
    int is64 = g_is64;
    if (i < EE) {
        int s = edge_at(ei, is64, i);
        int d = edge_at(ei, is64, (size_t)EE + i);
        atomicAdd(&g_outdeg[s], 1);
        atomicAdd(&g_indeg[d], 1);
    }
}

__global__ void norm_kernel() {
    int i = blockIdx.x * blockDim.x + threadIdx.x;
    if (i < NN) {
        int od = g_outdeg[i];
        int id = g_indeg[i];
        g_nsrc[i] = od > 0 ? rsqrtf((float)od) : 0.0f;
        g_ndst[i] = id > 0 ? rsqrtf((float)id) : 0.0f;
    }
}

// ---------------- exclusive scan of indeg -> rowstart -------------------------
__global__ void scan1_kernel() {
    __shared__ int s[1024];
    int tid = threadIdx.x;
    int i = blockIdx.x * 1024 + tid;
    int v = (i < NN) ? g_indeg[i] : 0;
    s[tid] = v;
    __syncthreads();
    for (int off = 1; off < 1024; off <<= 1) {
        int t = (tid >= off) ? s[tid - off] : 0;
        __syncthreads();
        s[tid] += t;
        __syncthreads();
    }
    if (i < NN) g_rowstart[i] = s[tid] - v;  // exclusive
    if (tid == 1023) g_bsums[blockIdx.x] = s[1023];
}

__global__ void scan2_kernel(int nb) {
    if (threadIdx.x == 0) {
        int run = 0;
        for (int i = 0; i < nb; i++) {
            int t = g_bsums[i];
            g_bsums[i] = run;
            run += t;
        }
    }
}

__global__ void scan3_kernel() {
    int i = blockIdx.x * blockDim.x + threadIdx.x;
    if (i < NN) g_rowstart[i] += g_bsums[i >> 10];
    if (i == 0) g_rowstart[NN] = EE;
}

__global__ void fill_csr_kernel(const int* __restrict__ ei) {
    int i = blockIdx.x * blockDim.x + threadIdx.x;
    int is64 = g_is64;
    if (i < EE) {
        int s = edge_at(ei, is64, i);
        int d = edge_at(ei, is64, (size_t)EE + i);
        int p = atomicAdd(&g_cursor[d], 1);
        g_col[g_rowstart[d] + p] = s;
    }
}

// ---------------- copies ------------------------------------------------------
__global__ void copy_in_kernel(const float4* __restrict__ f) {
    int total = NN * 32;
    for (int i = blockIdx.x * blockDim.x + threadIdx.x; i < total;
         i += gridDim.x * blockDim.x)
        g_x4[i] = f[i];
}

__global__ void copy_out_kernel(float4* __restrict__ out) {
    int total = NN * 16;  // 100000 * 64 floats
    for (int i = blockIdx.x * blockDim.x + threadIdx.x; i < total;
         i += gridDim.x * blockDim.x)
        out[i] = g_x4[i];
}

// ---------------- GEMM (64-col tile): g_h[i, coff+j] = (g_x[i,:] @ W[:,coff+j]) * nsrc[i]
// 256 threads / 8 warps, each warp handles 4 rows per task.
// Shared: W tile as native float2 (32KB), x rows as native float4 (16KB).
__global__ __launch_bounds__(256) void gemm64_kernel(const float* __restrict__ W,
                                                     int ldw, int coff, int hstride) {
    __shared__ float2 sW[128 * 32];     // 32 KB
    __shared__ float4 sx[8 * 4 * 32];   // 16 KB

    int tid = threadIdx.x;
    for (int idx = tid; idx < 128 * 32; idx += 256) {
        int k = idx >> 5;
        int j2 = idx & 31;
        sW[idx] = make_float2(W[k * ldw + coff + 2 * j2],
                              W[k * ldw + coff + 2 * j2 + 1]);
    }
    __syncthreads();

    int warp = tid >> 5;
    int lane = tid & 31;
    float4* mysx = sx + warp * 128;
    float2* hdst = reinterpret_cast<float2*>(g_h4);

    int ntasks = NN >> 2;
    int stride = gridDim.x * 8;
    for (int task = blockIdx.x * 8 + warp; task < ntasks; task += stride) {
        int base = task * 4;
        __syncwarp();
        #pragma unroll
        for (int r = 0; r < 4; r++)
            mysx[r * 32 + lane] = g_x4[(size_t)(base + r) * 32 + lane];
        __syncwarp();

        float ax0 = 0.f, ay0 = 0.f, ax1 = 0.f, ay1 = 0.f;
        float ax2 = 0.f, ay2 = 0.f, ax3 = 0.f, ay3 = 0.f;

        #pragma unroll 4
        for (int k4 = 0; k4 < 32; k4++) {
            float4 xv0 = mysx[0 * 32 + k4];
            float4 xv1 = mysx[1 * 32 + k4];
            float4 xv2 = mysx[2 * 32 + k4];
            float4 xv3 = mysx[3 * 32 + k4];
            #pragma unroll
            for (int kk = 0; kk < 4; kk++) {
                float2 wv = sW[(k4 * 4 + kk) * 32 + lane];
                float x0 = (kk == 0) ? xv0.x : (kk == 1) ? xv0.y : (kk == 2) ? xv0.z : xv0.w;
                float x1 = (kk == 0) ? xv1.x : (kk == 1) ? xv1.y : (kk == 2) ? xv1.z : xv1.w;
                float x2 = (kk == 0) ? xv2.x : (kk == 1) ? xv2.y : (kk == 2) ? xv2.z : xv2.w;
                float x3 = (kk == 0) ? xv3.x : (kk == 1) ? xv3.y : (kk == 2) ? xv3.z : xv3.w;
                ax0 = fmaf(x0, wv.x, ax0); ay0 = fmaf(x0, wv.y, ay0);
                ax1 = fmaf(x1, wv.x, ax1); ay1 = fmaf(x1, wv.y, ay1);
                ax2 = fmaf(x2, wv.x, ax2); ay2 = fmaf(x2, wv.y, ay2);
                ax3 = fmaf(x3, wv.x, ax3); ay3 = fmaf(x3, wv.y, ay3);
            }
        }

        float s0 = g_nsrc[base + 0];
        float s1 = g_nsrc[base + 1];
        float s2 = g_nsrc[base + 2];
        float s3 = g_nsrc[base + 3];
        size_t r0 = ((size_t)(base + 0) * hstride + coff) >> 1;
        size_t r1 = ((size_t)(base + 1) * hstride + coff) >> 1;
        size_t r2 = ((size_t)(base + 2) * hstride + coff) >> 1;
        size_t r3 = ((size_t)(base + 3) * hstride + coff) >> 1;
        hdst[r0 + lane] = make_float2(ax0 * s0, ay0 * s0);
        hdst[r1 + lane] = make_float2(ax1 * s1, ay1 * s1);
        hdst[r2 + lane] = make_float2(ax2 * s2, ay2 * s2);
        hdst[r3 + lane] = make_float2(ax3 * s3, ay3 * s3);
    }
}

// ---------------- aggregate: g_x[d,:] = act( (sum_{s in N(d)} g_h[s,:]) * ndst[d] + b )
template <int DOUT, bool ACT>
__global__ __launch_bounds__(256) void aggregate_kernel(const float* __restrict__ b) {
    int warp = (blockIdx.x * 256 + threadIdx.x) >> 5;
    int lane = threadIdx.x & 31;
    if (warp >= NN) return;

    int s0 = g_rowstart[warp];
    int e0 = g_rowstart[warp + 1];
    float nd = g_ndst[warp];

    if (DOUT == 128) {
        const float4* __restrict__ h = g_h4;       // row stride = 32 float4
        float a0 = 0.f, a1 = 0.f, a2 = 0.f, a3 = 0.f;
        int i = s0;
        for (; i + 4 <= e0; i += 4) {
            int c0 = g_col[i], c1 = g_col[i + 1], c2 = g_col[i + 2], c3 = g_col[i + 3];
            float4 v0 = h[(size_t)c0 * 32 + lane];
            float4 v1 = h[(size_t)c1 * 32 + lane];
            float4 v2 = h[(size_t)c2 * 32 + lane];
            float4 v3 = h[(size_t)c3 * 32 + lane];
            a0 += (v0.x + v1.x) + (v2.x + v3.x);
            a1 += (v0.y + v1.y) + (v2.y + v3.y);
            a2 += (v0.z + v1.z) + (v2.z + v3.z);
            a3 += (v0.w + v1.w) + (v2.w + v3.w);
        }
        for (; i < e0; i++) {
            float4 v = h[(size_t)g_col[i] * 32 + lane];
            a0 += v.x; a1 += v.y; a2 += v.z; a3 += v.w;
        }
        float4 bb = ((const float4*)b)[lane];
        float4 o;
        o.x = a0 * nd + bb.x; o.y = a1 * nd + bb.y;
        o.z = a2 * nd + bb.z; o.w = a3 * nd + bb.w;
        if (ACT) { o.x = tanhf(o.x); o.y = tanhf(o.y); o.z = tanhf(o.z); o.w = tanhf(o.w); }
        g_x4[(size_t)warp * 32 + lane] = o;
    } else {
        const float2* __restrict__ h = reinterpret_cast<const float2*>(g_h4);  // stride 32 float2
        float a0 = 0.f, a1 = 0.f;
        int i = s0;
        for (; i + 4 <= e0; i += 4) {
            int c0 = g_col[i], c1 = g_col[i + 1], c2 = g_col[i + 2], c3 = g_col[i + 3];
            float2 v0 = h[(size_t)c0 * 32 + lane];
            float2 v1 = h[(size_t)c1 * 32 + lane];
            float2 v2 = h[(size_t)c2 * 32 + lane];
            float2 v3 = h[(size_t)c3 * 32 + lane];
            a0 += (v0.x + v1.x) + (v2.x + v3.x);
            a1 += (v0.y + v1.y) + (v2.y + v3.y);
        }
        for (; i < e0; i++) {
            float2 v = h[(size_t)g_col[i] * 32 + lane];
            a0 += v.x; a1 += v.y;
        }
        float2 bb = ((const float2*)b)[lane];
        float2 o;
        o.x = a0 * nd + bb.x; o.y = a1 * nd + bb.y;
        if (ACT) { o.x = tanhf(o.x); o.y = tanhf(o.y); }
        reinterpret_cast<float2*>(g_x4)[(size_t)warp * 32 + lane] = o;
    }
}

// ---------------- launch ------------------------------------------------------
extern "C" void kernel_launch(void* const* d_in, const int* in_sizes, int n_in,
                              void* d_out, int out_size) {
    const float* features = (const float*)d_in[0];
    const int*   ei       = (const int*)d_in[1];   // int32 OR little-endian int64 (detected)
    const float* W0 = (const float*)d_in[2];
    const float* b0 = (const float*)d_in[3];
    const float* W1 = (const float*)d_in[4];
    const float* b1 = (const float*)d_in[5];
    const float* W2 = (const float*)d_in[6];
    const float* b2 = (const float*)d_in[7];
    const float* W3 = (const float*)d_in[8];
    const float* b3 = (const float*)d_in[9];

    const int TB = 256;
    int nBlocksN = (NN + TB - 1) / TB;
    int nBlocksE = (EE + TB - 1) / TB;
    int nbScan   = (NN + 1023) / 1024;

    // ---- graph preprocessing (CSR by dst) ----
    detect_kernel<<<1, 128>>>(ei);
    zero_kernel<<<nBlocksN, TB>>>();
    degree_kernel<<<nBlocksE, TB>>>(ei);
    norm_kernel<<<nBlocksN, TB>>>();
    scan1_kernel<<<nbScan, 1024>>>();
    scan2_kernel<<<1, 32>>>(nbScan);
    scan3_kernel<<<nBlocksN, TB>>>();
    fill_csr_kernel<<<nBlocksE, TB>>>(ei);

    // ---- stage features into g_x ----
    copy_in_kernel<<<2048, TB>>>((const float4*)features);

    const int GEMM_BLOCKS = 592;
    const int AGG_BLOCKS  = (NN * 32 + TB - 1) / TB;

    // layer 0
    gemm64_kernel<<<GEMM_BLOCKS, TB>>>(W0, 128, 0,  128);
    gemm64_kernel<<<GEMM_BLOCKS, TB>>>(W0, 128, 64, 128);
    aggregate_kernel<128, true><<<AGG_BLOCKS, TB>>>(b0);
    // layer 1
    gemm64_kernel<<<GEMM_BLOCKS, TB>>>(W1, 128, 0,  128);
    gemm64_kernel<<<GEMM_BLOCKS, TB>>>(W1, 128, 64, 128);
    aggregate_kernel<128, true><<<AGG_BLOCKS, TB>>>(b1);
    // layer 2
    gemm64_kernel<<<GEMM_BLOCKS, TB>>>(W2, 128, 0,  128);
    gemm64_kernel<<<GEMM_BLOCKS, TB>>>(W2, 128, 64, 128);
    aggregate_kernel<128, true><<<AGG_BLOCKS, TB>>>(b2);
    // layer 3 (D_OUT=64, no activation)
    gemm64_kernel<<<GEMM_BLOCKS, TB>>>(W3, 64, 0, 64);
    aggregate_kernel<64, false><<<AGG_BLOCKS, TB>>>(b3);

    // ---- result -> d_out ----
    copy_out_kernel<<<2048, TB>>>((float4*)d_out);
}

// round 10
// speedup vs baseline: 1.4820x; 1.4820x over previous
#include <cuda_runtime.h>
#include <cuda_bf16.h>
#include <math.h>
#include <stdint.h>

#define NN 100000
#define EE 1600000

// ================= PTX helpers (portable: sm_80+ mma.sync path) ===============
__device__ __forceinline__ uint32_t smem_to_u32(const void* smem_ptr) {
    uint32_t addr;
    asm("{ .reg .u64 tmp; cvta.to.shared.u64 tmp, %1; cvt.u32.u64 %0, tmp; }"
        : "=r"(addr) : "l"(smem_ptr));
    return addr;
}

#define LDSM_X4(r0, r1, r2, r3, addr) \
    asm volatile("ldmatrix.sync.aligned.m8n8.x4.shared.b16 {%0,%1,%2,%3}, [%4];" \
                 : "=r"(r0), "=r"(r1), "=r"(r2), "=r"(r3) : "r"(addr))

#define LDSM_X2(r0, r1, addr) \
    asm volatile("ldmatrix.sync.aligned.m8n8.x2.shared.b16 {%0,%1}, [%2];" \
                 : "=r"(r0), "=r"(r1) : "r"(addr))

#define MMA_BF16(d, a0, a1, a2, a3, b0, b1) \
    asm volatile("mma.sync.aligned.m16n8k16.row.col.f32.bf16.bf16.f32 " \
                 "{%0,%1,%2,%3}, {%4,%5,%6,%7}, {%8,%9}, {%0,%1,%2,%3};" \
                 : "+f"((d)[0]), "+f"((d)[1]), "+f"((d)[2]), "+f"((d)[3]) \
                 : "r"(a0), "r"(a1), "r"(a2), "r"(a3), "r"(b0), "r"(b1))

// ---------------- scratch (static device globals; no allocations) -------------
__device__ float4 g_x4[(size_t)NN * 32];   // 100000 x 128 floats (activations)
__device__ float4 g_h4[(size_t)NN * 32];   // gemm output / gather input
__device__ int    g_indeg[NN];
__device__ int    g_outdeg[NN];
__device__ float  g_nsrc[NN];
__device__ float  g_ndst[NN];
__device__ int    g_rowstart[NN + 1];
__device__ int    g_cursor[NN];
__device__ int    g_col[EE];
__device__ int    g_bsums[128];
__device__ int    g_is64;

__device__ __forceinline__ int edge_at(const int* __restrict__ w, int is64, size_t idx) {
    return is64 ? w[idx << 1] : w[idx];
}

// ---------------- dtype detect ------------------------------------------------
__global__ void detect_kernel(const int* __restrict__ w) {
    __shared__ int nz;
    if (threadIdx.x == 0) nz = 0;
    __syncthreads();
    int v = w[2 * threadIdx.x + 1];
    if (v != 0) atomicAdd(&nz, 1);
    __syncthreads();
    if (threadIdx.x == 0) g_is64 = (nz == 0) ? 1 : 0;
}

// ---------------- degree / norms --------------------------------------------
__global__ void zero_kernel() {
    int i = blockIdx.x * blockDim.x + threadIdx.x;
    if (i < NN) {
        g_indeg[i] = 0;
        g_outdeg[i] = 0;
        g_cursor[i] = 0;
    }
}

__global__ void degree_kernel(const int* __restrict__ ei) {
    int i = blockIdx.x * blockDim.x + threadIdx.x;
    int is64 = g_is64;
    if (i < EE) {
        int s = edge_at(ei, is64, i);
        int d = edge_at(ei, is64, (size_t)EE + i);
        atomicAdd(&g_outdeg[s], 1);
        atomicAdd(&g_indeg[d], 1);
    }
}

__global__ void norm_kernel() {
    int i = blockIdx.x * blockDim.x + threadIdx.x;
    if (i < NN) {
        int od = g_outdeg[i];
        int id = g_indeg[i];
        g_nsrc[i] = od > 0 ? rsqrtf((float)od) : 0.0f;
        g_ndst[i] = id > 0 ? rsqrtf((float)id) : 0.0f;
    }
}

// ---------------- exclusive scan of indeg -> rowstart -------------------------
__global__ void scan1_kernel() {
    __shared__ int s[1024];
    int tid = threadIdx.x;
    int i = blockIdx.x * 1024 + tid;
    int v = (i < NN) ? g_indeg[i] : 0;
    s[tid] = v;
    __syncthreads();
    for (int off = 1; off < 1024; off <<= 1) {
        int t = (tid >= off) ? s[tid - off] : 0;
        __syncthreads();
        s[tid] += t;
        __syncthreads();
    }
    if (i < NN) g_rowstart[i] = s[tid] - v;
    if (tid == 1023) g_bsums[blockIdx.x] = s[1023];
}

__global__ void scan2_kernel(int nb) {
    if (threadIdx.x == 0) {
        int run = 0;
        for (int i = 0; i < nb; i++) {
            int t = g_bsums[i];
            g_bsums[i] = run;
            run += t;
        }
    }
}

__global__ void scan3_kernel() {
    int i = blockIdx.x * blockDim.x + threadIdx.x;
    if (i < NN) g_rowstart[i] += g_bsums[i >> 10];
    if (i == 0) g_rowstart[NN] = EE;
}

__global__ void fill_csr_kernel(const int* __restrict__ ei) {
    int i = blockIdx.x * blockDim.x + threadIdx.x;
    int is64 = g_is64;
    if (i < EE) {
        int s = edge_at(ei, is64, i);
        int d = edge_at(ei, is64, (size_t)EE + i);
        int p = atomicAdd(&g_cursor[d], 1);
        g_col[g_rowstart[d] + p] = s;
    }
}

// ================ tensor-core GEMM via mma.sync (bf16x3 split) ================
// g_h[i,:] = (x[i,:] @ W) * nsrc[i].  Per CTA: 128-row x NOUT tile; 8 warps,
// warp w owns rows [16w,16w+16). X and W^T staged in SMEM as bf16 hi/lo with
// 16B-chunk XOR swizzle (conflict-free ldmatrix). D = xh@wh + xh@wl + xl@wh.
__device__ __forceinline__ uint32_t bfpack(float a, float b) {
    return (uint32_t)__bfloat16_as_ushort(__float2bfloat16(a))
         | ((uint32_t)__bfloat16_as_ushort(__float2bfloat16(b)) << 16);
}
__device__ __forceinline__ float bflo(float v) {
    return v - __bfloat162float(__float2bfloat16(v));
}

template <int NOUT, bool EXT>
__global__ __launch_bounds__(256) void gemm_mma_kernel(const float* __restrict__ xext,
                                                       const float* __restrict__ W) {
    constexpr int NT = NOUT / 8;                  // n-tiles of 8
    constexpr int WBYTES = NOUT * 256;            // one W^T split
    extern __shared__ char smem[];
    uint32_t sbase = smem_to_u32(smem);
    const uint32_t XHI = 0, XLO = 32768, WHI = 65536, WLO = 65536 + WBYTES;

    int tid = threadIdx.x;
    int lane = tid & 31;
    int warp = tid >> 5;

    // ---- stage W^T (n rows, 128 k cols) as bf16 hi/lo, swizzled ----
    for (int idx = tid; idx < NOUT * 16; idx += 256) {
        int n = idx >> 4;
        int c = idx & 15;                         // 16B chunk = 8 k values
        uint32_t hi[4], lo[4];
        #pragma unroll
        for (int j = 0; j < 4; j++) {
            float w0 = W[(c * 8 + 2 * j)     * NOUT + n];
            float w1 = W[(c * 8 + 2 * j + 1) * NOUT + n];
            hi[j] = bfpack(w0, w1);
            lo[j] = bfpack(bflo(w0), bflo(w1));
        }
        uint32_t off = (uint32_t)n * 256 + (uint32_t)((c ^ (n & 7)) << 4);
        *(uint4*)(smem + WHI + off) = make_uint4(hi[0], hi[1], hi[2], hi[3]);
        *(uint4*)(smem + WLO + off) = make_uint4(lo[0], lo[1], lo[2], lo[3]);
    }

    const float4* xsrc = EXT ? (const float4*)xext : (const float4*)g_x4;
    float* gh = (float*)g_h4;
    int ntiles = (NN + 127) >> 7;                 // 782

    // A-fragment ldmatrix address components (per lane)
    int arow = lane & 15;                         // row within warp strip
    int asel = lane >> 4;                         // chunk select 0/1
    // B-fragment address components
    int bn   = lane & 7;                          // row within n-tile
    int bsel = (lane >> 3) & 1;                   // chunk select 0/1

    for (int tile = blockIdx.x; tile < ntiles; tile += gridDim.x) {
        __syncthreads();   // protect smem X from previous iteration's readers

        // ---- stage X tile (128 rows x 128 cols) as bf16 hi/lo, swizzled ----
        {
            int r = tid >> 1;                     // 0..127
            int half = tid & 1;                   // 0/1 -> cols 0-63 / 64-127
            int grow = tile * 128 + r;
            bool valid = grow < NN;
            #pragma unroll
            for (int c8 = 0; c8 < 8; c8++) {
                int c = half * 8 + c8;            // chunk index (8 floats)
                float4 v0, v1;
                if (valid) {
                    v0 = xsrc[(size_t)grow * 32 + c * 2];
                    v1 = xsrc[(size_t)grow * 32 + c * 2 + 1];
                } else {
                    v0 = make_float4(0.f, 0.f, 0.f, 0.f);
                    v1 = v0;
                }
                uint32_t off = (uint32_t)r * 256 + (uint32_t)((c ^ (r & 7)) << 4);
                *(uint4*)(smem + XHI + off) = make_uint4(
                    bfpack(v0.x, v0.y), bfpack(v0.z, v0.w),
                    bfpack(v1.x, v1.y), bfpack(v1.z, v1.w));
                *(uint4*)(smem + XLO + off) = make_uint4(
                    bfpack(bflo(v0.x), bflo(v0.y)), bfpack(bflo(v0.z), bflo(v0.w)),
                    bfpack(bflo(v1.x), bflo(v1.y)), bfpack(bflo(v1.z), bflo(v1.w)));
            }
        }
        __syncthreads();

        // ---- MMA mainloop ----
        float acc[NT][4];
        #pragma unroll
        for (int nt = 0; nt < NT; nt++)
            #pragma unroll
            for (int q = 0; q < 4; q++) acc[nt][q] = 0.0f;

        #pragma unroll
        for (int kt = 0; kt < 8; kt++) {
            int r = warp * 16 + arow;
            int achunk = 2 * kt + asel;
            uint32_t aoff = (uint32_t)r * 256 + (uint32_t)((achunk ^ (r & 7)) << 4);
            uint32_t ah0, ah1, ah2, ah3, al0, al1, al2, al3;
            LDSM_X4(ah0, ah1, ah2, ah3, sbase + XHI + aoff);
            LDSM_X4(al0, al1, al2, al3, sbase + XLO + aoff);

            #pragma unroll
            for (int nt = 0; nt < NT; nt++) {
                int n = nt * 8 + bn;
                int bchunk = 2 * kt + bsel;
                uint32_t boff = (uint32_t)n * 256 + (uint32_t)((bchunk ^ (n & 7)) << 4);
                uint32_t bh0, bh1, bl0, bl1;
                LDSM_X2(bh0, bh1, sbase + WHI + boff);
                LDSM_X2(bl0, bl1, sbase + WLO + boff);
                MMA_BF16(acc[nt], ah0, ah1, ah2, ah3, bh0, bh1);
                MMA_BF16(acc[nt], ah0, ah1, ah2, ah3, bl0, bl1);
                MMA_BF16(acc[nt], al0, al1, al2, al3, bh0, bh1);
            }
        }

        // ---- epilogue: scale by nsrc, write g_h ----
        int r0 = tile * 128 + warp * 16 + (lane >> 2);
        int r1 = r0 + 8;
        bool v0 = r0 < NN, v1 = r1 < NN;
        float s0 = v0 ? g_nsrc[r0] : 0.0f;
        float s1 = v1 ? g_nsrc[r1] : 0.0f;
        #pragma unroll
        for (int nt = 0; nt < NT; nt++) {
            int col = nt * 8 + 2 * (lane & 3);
            if (v0) *(float2*)(gh + (size_t)r0 * NOUT + col) =
                make_float2(acc[nt][0] * s0, acc[nt][1] * s0);
            if (v1) *(float2*)(gh + (size_t)r1 * NOUT + col) =
                make_float2(acc[nt][2] * s1, acc[nt][3] * s1);
        }
    }
}

// ---------------- aggregate: dst[d,:] = act( (sum g_h[s,:]) * ndst[d] + b ) ----
template <int DOUT, bool ACT, bool TOOUT>
__global__ __launch_bounds__(256) void aggregate_kernel(const float* __restrict__ b,
                                                        float* __restrict__ outext) {
    int warp = (blockIdx.x * 256 + threadIdx.x) >> 5;
    int lane = threadIdx.x & 31;
    if (warp >= NN) return;

    int s0 = g_rowstart[warp];
    int e0 = g_rowstart[warp + 1];
    float nd = g_ndst[warp];

    if (DOUT == 128) {
        const float4* __restrict__ h = g_h4;
        float a0 = 0.f, a1 = 0.f, a2 = 0.f, a3 = 0.f;
        int i = s0;
        for (; i + 4 <= e0; i += 4) {
            int c0 = g_col[i], c1 = g_col[i + 1], c2 = g_col[i + 2], c3 = g_col[i + 3];
            float4 v0 = h[(size_t)c0 * 32 + lane];
            float4 v1 = h[(size_t)c1 * 32 + lane];
            float4 v2 = h[(size_t)c2 * 32 + lane];
            float4 v3 = h[(size_t)c3 * 32 + lane];
            a0 += (v0.x + v1.x) + (v2.x + v3.x);
            a1 += (v0.y + v1.y) + (v2.y + v3.y);
            a2 += (v0.z + v1.z) + (v2.z + v3.z);
            a3 += (v0.w + v1.w) + (v2.w + v3.w);
        }
        for (; i < e0; i++) {
            float4 v = h[(size_t)g_col[i] * 32 + lane];
            a0 += v.x; a1 += v.y; a2 += v.z; a3 += v.w;
        }
        float4 bb = ((const float4*)b)[lane];
        float4 o;
        o.x = a0 * nd + bb.x; o.y = a1 * nd + bb.y;
        o.z = a2 * nd + bb.z; o.w = a3 * nd + bb.w;
        if (ACT) { o.x = tanhf(o.x); o.y = tanhf(o.y); o.z = tanhf(o.z); o.w = tanhf(o.w); }
        if (TOOUT) ((float4*)(outext + (size_t)warp * 128))[lane] = o;
        else       g_x4[(size_t)warp * 32 + lane] = o;
    } else {
        const float2* __restrict__ h = reinterpret_cast<const float2*>(g_h4);
        float a0 = 0.f, a1 = 0.f;
        int i = s0;
        for (; i + 4 <= e0; i += 4) {
            int c0 = g_col[i], c1 = g_col[i + 1], c2 = g_col[i + 2], c3 = g_col[i + 3];
            float2 v0 = h[(size_t)c0 * 32 + lane];
            float2 v1 = h[(size_t)c1 * 32 + lane];
            float2 v2 = h[(size_t)c2 * 32 + lane];
            float2 v3 = h[(size_t)c3 * 32 + lane];
            a0 += (v0.x + v1.x) + (v2.x + v3.x);
            a1 += (v0.y + v1.y) + (v2.y + v3.y);
        }
        for (; i < e0; i++) {
            float2 v = h[(size_t)g_col[i] * 32 + lane];
            a0 += v.x; a1 += v.y;
        }
        float2 bb = ((const float2*)b)[lane];
        float2 o;
        o.x = a0 * nd + bb.x; o.y = a1 * nd + bb.y;
        if (ACT) { o.x = tanhf(o.x); o.y = tanhf(o.y); }
        if (TOOUT) ((float2*)(outext + (size_t)warp * 64))[lane] = o;
        else       reinterpret_cast<float2*>(g_x4)[(size_t)warp * 32 + lane] = o;
    }
}

// ---------------- launch ------------------------------------------------------
extern "C" void kernel_launch(void* const* d_in, const int* in_sizes, int n_in,
                              void* d_out, int out_size) {
    const float* features = (const float*)d_in[0];
    const int*   ei       = (const int*)d_in[1];
    const float* W0 = (const float*)d_in[2];
    const float* b0 = (const float*)d_in[3];
    const float* W1 = (const float*)d_in[4];
    const float* b1 = (const float*)d_in[5];
    const float* W2 = (const float*)d_in[6];
    const float* b2 = (const float*)d_in[7];
    const float* W3 = (const float*)d_in[8];
    const float* b3 = (const float*)d_in[9];
    float* out = (float*)d_out;

    const int TB = 256;
    int nBlocksN = (NN + TB - 1) / TB;
    int nBlocksE = (EE + TB - 1) / TB;
    int nbScan   = (NN + 1023) / 1024;

    // dynamic smem: X hi/lo (64KB) + W^T hi/lo
    const int SMEM128 = 65536 + 128 * 256 * 2;   // 131072
    const int SMEM64  = 65536 + 64  * 256 * 2;   //  98304
    cudaFuncSetAttribute(gemm_mma_kernel<128, true>,
                         cudaFuncAttributeMaxDynamicSharedMemorySize, SMEM128);
    cudaFuncSetAttribute(gemm_mma_kernel<128, false>,
                         cudaFuncAttributeMaxDynamicSharedMemorySize, SMEM128);
    cudaFuncSetAttribute(gemm_mma_kernel<64, false>,
                         cudaFuncAttributeMaxDynamicSharedMemorySize, SMEM64);

    // ---- graph preprocessing (CSR by dst) ----
    detect_kernel<<<1, 128>>>(ei);
    zero_kernel<<<nBlocksN, TB>>>();
    degree_kernel<<<nBlocksE, TB>>>(ei);
    norm_kernel<<<nBlocksN, TB>>>();
    scan1_kernel<<<nbScan, 1024>>>();
    scan2_kernel<<<1, 32>>>(nbScan);
    scan3_kernel<<<nBlocksN, TB>>>();
    fill_csr_kernel<<<nBlocksE, TB>>>(ei);

    const int GEMM_BLOCKS = 148;   // 1 CTA/SM (128KB smem)
    const int AGG_BLOCKS  = (NN * 32 + TB - 1) / TB;

    // layer 0
    gemm_mma_kernel<128, true><<<GEMM_BLOCKS, TB, SMEM128>>>(features, W0);
    aggregate_kernel<128, true, false><<<AGG_BLOCKS, TB>>>(b0, nullptr);
    // layer 1
    gemm_mma_kernel<128, false><<<GEMM_BLOCKS, TB, SMEM128>>>(nullptr, W1);
    aggregate_kernel<128, true, false><<<AGG_BLOCKS, TB>>>(b1, nullptr);
    // layer 2
    gemm_mma_kernel<128, false><<<GEMM_BLOCKS, TB, SMEM128>>>(nullptr, W2);
    aggregate_kernel<128, true, false><<<AGG_BLOCKS, TB>>>(b2, nullptr);
    // layer 3 (D_OUT=64, no activation) -> d_out
    gemm_mma_kernel<64, false><<<GEMM_BLOCKS, TB, SMEM64>>>(nullptr, W3);
    aggregate_kernel<64, false, true><<<AGG_BLOCKS, TB>>>(b3, out);
}

// round 11
// speedup vs baseline: 1.5725x; 1.0611x over previous
#include <cuda_runtime.h>
#include <cuda_bf16.h>
#include <cuda_fp16.h>
#include <math.h>
#include <stdint.h>

#define NN 100000
#define EE 1600000

// ================= PTX helpers (portable: sm_80+ mma.sync path) ===============
__device__ __forceinline__ uint32_t smem_to_u32(const void* smem_ptr) {
    uint32_t addr;
    asm("{ .reg .u64 tmp; cvta.to.shared.u64 tmp, %1; cvt.u32.u64 %0, tmp; }"
        : "=r"(addr) : "l"(smem_ptr));
    return addr;
}

#define LDSM_X4(r0, r1, r2, r3, addr) \
    asm volatile("ldmatrix.sync.aligned.m8n8.x4.shared.b16 {%0,%1,%2,%3}, [%4];" \
                 : "=r"(r0), "=r"(r1), "=r"(r2), "=r"(r3) : "r"(addr))

#define LDSM_X2(r0, r1, addr) \
    asm volatile("ldmatrix.sync.aligned.m8n8.x2.shared.b16 {%0,%1}, [%2];" \
                 : "=r"(r0), "=r"(r1) : "r"(addr))

#define MMA_BF16(d, a0, a1, a2, a3, b0, b1) \
    asm volatile("mma.sync.aligned.m16n8k16.row.col.f32.bf16.bf16.f32 " \
                 "{%0,%1,%2,%3}, {%4,%5,%6,%7}, {%8,%9}, {%0,%1,%2,%3};" \
                 : "+f"((d)[0]), "+f"((d)[1]), "+f"((d)[2]), "+f"((d)[3]) \
                 : "r"(a0), "r"(a1), "r"(a2), "r"(a3), "r"(b0), "r"(b1))

// ---------------- scratch (static device globals; no allocations) -------------
__device__ float4 g_x4[(size_t)NN * 32];   // 100000 x 128 floats (activations)
__device__ float4 g_h4[(size_t)NN * 32];   // gemm output (fp32 OR fp16 view)
__device__ int    g_indeg[NN];
__device__ int    g_outdeg[NN];
__device__ float  g_nsrc[NN];
__device__ float  g_ndst[NN];
__device__ int    g_rowstart[NN + 1];
__device__ int    g_cursor[NN];
__device__ int    g_col[EE];
__device__ int    g_bsums[128];
__device__ int    g_is64;

__device__ __forceinline__ int edge_at(const int* __restrict__ w, int is64, size_t idx) {
    return is64 ? w[idx << 1] : w[idx];
}

// ---------------- dtype detect ------------------------------------------------
__global__ void detect_kernel(const int* __restrict__ w) {
    __shared__ int nz;
    if (threadIdx.x == 0) nz = 0;
    __syncthreads();
    int v = w[2 * threadIdx.x + 1];
    if (v != 0) atomicAdd(&nz, 1);
    __syncthreads();
    if (threadIdx.x == 0) g_is64 = (nz == 0) ? 1 : 0;
}

// ---------------- degree / norms --------------------------------------------
__global__ void zero_kernel() {
    int i = blockIdx.x * blockDim.x + threadIdx.x;
    if (i < NN) {
        g_indeg[i] = 0;
        g_outdeg[i] = 0;
        g_cursor[i] = 0;
    }
}

__global__ void degree_kernel(const int* __restrict__ ei) {
    int i = blockIdx.x * blockDim.x + threadIdx.x;
    int is64 = g_is64;
    if (i < EE) {
        int s = edge_at(ei, is64, i);
        int d = edge_at(ei, is64, (size_t)EE + i);
        atomicAdd(&g_outdeg[s], 1);
        atomicAdd(&g_indeg[d], 1);
    }
}

__global__ void norm_kernel() {
    int i = blockIdx.x * blockDim.x + threadIdx.x;
    if (i < NN) {
        int od = g_outdeg[i];
        int id = g_indeg[i];
        g_nsrc[i] = od > 0 ? rsqrtf((float)od) : 0.0f;
        g_ndst[i] = id > 0 ? rsqrtf((float)id) : 0.0f;
    }
}

// ---------------- exclusive scan of indeg -> rowstart -------------------------
__global__ void scan1_kernel() {
    __shared__ int s[1024];
    int tid = threadIdx.x;
    int i = blockIdx.x * 1024 + tid;
    int v = (i < NN) ? g_indeg[i] : 0;
    s[tid] = v;
    __syncthreads();
    for (int off = 1; off < 1024; off <<= 1) {
        int t = (tid >= off) ? s[tid - off] : 0;
        __syncthreads();
        s[tid] += t;
        __syncthreads();
    }
    if (i < NN) g_rowstart[i] = s[tid] - v;
    if (tid == 1023) g_bsums[blockIdx.x] = s[1023];
}

__global__ void scan2_kernel(int nb) {
    if (threadIdx.x == 0) {
        int run = 0;
        for (int i = 0; i < nb; i++) {
            int t = g_bsums[i];
            g_bsums[i] = run;
            run += t;
        }
    }
}

__global__ void scan3_kernel() {
    int i = blockIdx.x * blockDim.x + threadIdx.x;
    if (i < NN) g_rowstart[i] += g_bsums[i >> 10];
    if (i == 0) g_rowstart[NN] = EE;
}

__global__ void fill_csr_kernel(const int* __restrict__ ei) {
    int i = blockIdx.x * blockDim.x + threadIdx.x;
    int is64 = g_is64;
    if (i < EE) {
        int s = edge_at(ei, is64, i);
        int d = edge_at(ei, is64, (size_t)EE + i);
        int p = atomicAdd(&g_cursor[d], 1);
        g_col[g_rowstart[d] + p] = s;
    }
}

// ================ tensor-core GEMM via mma.sync (bf16x3 split) ================
// g_h[i,:] = (x[i,:] @ W) * nsrc[i].  HALFOUT: store h as fp16 (layers 0-2).
__device__ __forceinline__ uint32_t bfpack(float a, float b) {
    return (uint32_t)__bfloat16_as_ushort(__float2bfloat16(a))
         | ((uint32_t)__bfloat16_as_ushort(__float2bfloat16(b)) << 16);
}
__device__ __forceinline__ float bflo(float v) {
    return v - __bfloat162float(__float2bfloat16(v));
}

template <int NOUT, bool EXT, bool HALFOUT>
__global__ __launch_bounds__(256) void gemm_mma_kernel(const float* __restrict__ xext,
                                                       const float* __restrict__ W) {
    constexpr int NT = NOUT / 8;
    constexpr int WBYTES = NOUT * 256;
    extern __shared__ char smem[];
    uint32_t sbase = smem_to_u32(smem);
    const uint32_t XHI = 0, XLO = 32768, WHI = 65536, WLO = 65536 + WBYTES;

    int tid = threadIdx.x;
    int lane = tid & 31;
    int warp = tid >> 5;

    // ---- stage W^T (n rows, 128 k cols) as bf16 hi/lo, swizzled ----
    for (int idx = tid; idx < NOUT * 16; idx += 256) {
        int n = idx >> 4;
        int c = idx & 15;
        uint32_t hi[4], lo[4];
        #pragma unroll
        for (int j = 0; j < 4; j++) {
            float w0 = W[(c * 8 + 2 * j)     * NOUT + n];
            float w1 = W[(c * 8 + 2 * j + 1) * NOUT + n];
            hi[j] = bfpack(w0, w1);
            lo[j] = bfpack(bflo(w0), bflo(w1));
        }
        uint32_t off = (uint32_t)n * 256 + (uint32_t)((c ^ (n & 7)) << 4);
        *(uint4*)(smem + WHI + off) = make_uint4(hi[0], hi[1], hi[2], hi[3]);
        *(uint4*)(smem + WLO + off) = make_uint4(lo[0], lo[1], lo[2], lo[3]);
    }

    const float4* xsrc = EXT ? (const float4*)xext : (const float4*)g_x4;
    float* gh = (float*)g_h4;
    __half2* hh = reinterpret_cast<__half2*>(g_h4);
    int ntiles = (NN + 127) >> 7;

    int arow = lane & 15;
    int asel = lane >> 4;
    int bn   = lane & 7;
    int bsel = (lane >> 3) & 1;

    for (int tile = blockIdx.x; tile < ntiles; tile += gridDim.x) {
        __syncthreads();

        // ---- stage X tile (128 x 128) as bf16 hi/lo, swizzled ----
        {
            int r = tid >> 1;
            int half = tid & 1;
            int grow = tile * 128 + r;
            bool valid = grow < NN;
            #pragma unroll
            for (int c8 = 0; c8 < 8; c8++) {
                int c = half * 8 + c8;
                float4 v0, v1;
                if (valid) {
                    v0 = xsrc[(size_t)grow * 32 + c * 2];
                    v1 = xsrc[(size_t)grow * 32 + c * 2 + 1];
                } else {
                    v0 = make_float4(0.f, 0.f, 0.f, 0.f);
                    v1 = v0;
                }
                uint32_t off = (uint32_t)r * 256 + (uint32_t)((c ^ (r & 7)) << 4);
                *(uint4*)(smem + XHI + off) = make_uint4(
                    bfpack(v0.x, v0.y), bfpack(v0.z, v0.w),
                    bfpack(v1.x, v1.y), bfpack(v1.z, v1.w));
                *(uint4*)(smem + XLO + off) = make_uint4(
                    bfpack(bflo(v0.x), bflo(v0.y)), bfpack(bflo(v0.z), bflo(v0.w)),
                    bfpack(bflo(v1.x), bflo(v1.y)), bfpack(bflo(v1.z), bflo(v1.w)));
            }
        }
        __syncthreads();

        // ---- MMA mainloop ----
        float acc[NT][4];
        #pragma unroll
        for (int nt = 0; nt < NT; nt++)
            #pragma unroll
            for (int q = 0; q < 4; q++) acc[nt][q] = 0.0f;

        #pragma unroll
        for (int kt = 0; kt < 8; kt++) {
            int r = warp * 16 + arow;
            int achunk = 2 * kt + asel;
            uint32_t aoff = (uint32_t)r * 256 + (uint32_t)((achunk ^ (r & 7)) << 4);
            uint32_t ah0, ah1, ah2, ah3, al0, al1, al2, al3;
            LDSM_X4(ah0, ah1, ah2, ah3, sbase + XHI + aoff);
            LDSM_X4(al0, al1, al2, al3, sbase + XLO + aoff);

            #pragma unroll
            for (int nt = 0; nt < NT; nt++) {
                int n = nt * 8 + bn;
                int bchunk = 2 * kt + bsel;
                uint32_t boff = (uint32_t)n * 256 + (uint32_t)((bchunk ^ (n & 7)) << 4);
                uint32_t bh0, bh1, bl0, bl1;
                LDSM_X2(bh0, bh1, sbase + WHI + boff);
                LDSM_X2(bl0, bl1, sbase + WLO + boff);
                MMA_BF16(acc[nt], ah0, ah1, ah2, ah3, bh0, bh1);
                MMA_BF16(acc[nt], ah0, ah1, ah2, ah3, bl0, bl1);
                MMA_BF16(acc[nt], al0, al1, al2, al3, bh0, bh1);
            }
        }

        // ---- epilogue: scale by nsrc, write g_h (fp32 or fp16) ----
        int r0 = tile * 128 + warp * 16 + (lane >> 2);
        int r1 = r0 + 8;
        bool v0 = r0 < NN, v1 = r1 < NN;
        float s0 = v0 ? g_nsrc[r0] : 0.0f;
        float s1 = v1 ? g_nsrc[r1] : 0.0f;
        #pragma unroll
        for (int nt = 0; nt < NT; nt++) {
            if (HALFOUT) {
                int h2idx = nt * 4 + (lane & 3);              // covers cols 2*h2idx, +1
                if (v0) hh[(size_t)r0 * (NOUT / 2) + h2idx] =
                    __floats2half2_rn(acc[nt][0] * s0, acc[nt][1] * s0);
                if (v1) hh[(size_t)r1 * (NOUT / 2) + h2idx] =
                    __floats2half2_rn(acc[nt][2] * s1, acc[nt][3] * s1);
            } else {
                int col = nt * 8 + 2 * (lane & 3);
                if (v0) *(float2*)(gh + (size_t)r0 * NOUT + col) =
                    make_float2(acc[nt][0] * s0, acc[nt][1] * s0);
                if (v1) *(float2*)(gh + (size_t)r1 * NOUT + col) =
                    make_float2(acc[nt][2] * s1, acc[nt][3] * s1);
            }
        }
    }
}

// -------- aggregate (fp16 h, DOUT=128): g_x[d,:] = tanh(sum*ndst + b) ---------
// Row = 64 half2 = 32 x 8B. Lane loads one float2 (2 half2 = cols 4L..4L+3).
template <bool ACT>
__global__ __launch_bounds__(256) void aggregate_half_kernel(const float* __restrict__ b) {
    int warp = (blockIdx.x * 256 + threadIdx.x) >> 5;
    int lane = threadIdx.x & 31;
    if (warp >= NN) return;

    const float2* __restrict__ h = reinterpret_cast<const float2*>(g_h4);  // stride 32
    int s0 = g_rowstart[warp];
    int e0 = g_rowstart[warp + 1];
    float nd = g_ndst[warp];

    float a0 = 0.f, a1 = 0.f, a2 = 0.f, a3 = 0.f;
    int i = s0;
    for (; i + 4 <= e0; i += 4) {
        int c0 = g_col[i], c1 = g_col[i + 1], c2 = g_col[i + 2], c3 = g_col[i + 3];
        float2 r0 = h[(size_t)c0 * 32 + lane];
        float2 r1 = h[(size_t)c1 * 32 + lane];
        float2 r2 = h[(size_t)c2 * 32 + lane];
        float2 r3 = h[(size_t)c3 * 32 + lane];
        float2 f;
        f = __half22float2(*reinterpret_cast<__half2*>(&r0.x)); a0 += f.x; a1 += f.y;
        f = __half22float2(*reinterpret_cast<__half2*>(&r0.y)); a2 += f.x; a3 += f.y;
        f = __half22float2(*reinterpret_cast<__half2*>(&r1.x)); a0 += f.x; a1 += f.y;
        f = __half22float2(*reinterpret_cast<__half2*>(&r1.y)); a2 += f.x; a3 += f.y;
        f = __half22float2(*reinterpret_cast<__half2*>(&r2.x)); a0 += f.x; a1 += f.y;
        f = __half22float2(*reinterpret_cast<__half2*>(&r2.y)); a2 += f.x; a3 += f.y;
        f = __half22float2(*reinterpret_cast<__half2*>(&r3.x)); a0 += f.x; a1 += f.y;
        f = __half22float2(*reinterpret_cast<__half2*>(&r3.y)); a2 += f.x; a3 += f.y;
    }
    for (; i < e0; i++) {
        float2 r0 = h[(size_t)g_col[i] * 32 + lane];
        float2 f;
        f = __half22float2(*reinterpret_cast<__half2*>(&r0.x)); a0 += f.x; a1 += f.y;
        f = __half22float2(*reinterpret_cast<__half2*>(&r0.y)); a2 += f.x; a3 += f.y;
    }

    float4 bb = ((const float4*)b)[lane];
    float4 o;
    o.x = a0 * nd + bb.x; o.y = a1 * nd + bb.y;
    o.z = a2 * nd + bb.z; o.w = a3 * nd + bb.w;
    if (ACT) { o.x = tanhf(o.x); o.y = tanhf(o.y); o.z = tanhf(o.z); o.w = tanhf(o.w); }
    g_x4[(size_t)warp * 32 + lane] = o;
}

// -------- aggregate (fp32 h, DOUT=64): out[d,:] = sum*ndst + b ----------------
__global__ __launch_bounds__(256) void aggregate64_kernel(const float* __restrict__ b,
                                                          float* __restrict__ outext) {
    int warp = (blockIdx.x * 256 + threadIdx.x) >> 5;
    int lane = threadIdx.x & 31;
    if (warp >= NN) return;

    const float2* __restrict__ h = reinterpret_cast<const float2*>(g_h4);  // stride 32
    int s0 = g_rowstart[warp];
    int e0 = g_rowstart[warp + 1];
    float nd = g_ndst[warp];

    float a0 = 0.f, a1 = 0.f;
    int i = s0;
    for (; i + 4 <= e0; i += 4) {
        int c0 = g_col[i], c1 = g_col[i + 1], c2 = g_col[i + 2], c3 = g_col[i + 3];
        float2 v0 = h[(size_t)c0 * 32 + lane];
        float2 v1 = h[(size_t)c1 * 32 + lane];
        float2 v2 = h[(size_t)c2 * 32 + lane];
        float2 v3 = h[(size_t)c3 * 32 + lane];
        a0 += (v0.x + v1.x) + (v2.x + v3.x);
        a1 += (v0.y + v1.y) + (v2.y + v3.y);
    }
    for (; i < e0; i++) {
        float2 v = h[(size_t)g_col[i] * 32 + lane];
        a0 += v.x; a1 += v.y;
    }

    float2 bb = ((const float2*)b)[lane];
    float2 o;
    o.x = a0 * nd + bb.x; o.y = a1 * nd + bb.y;
    ((float2*)(outext + (size_t)warp * 64))[lane] = o;
}

// ---------------- launch ------------------------------------------------------
extern "C" void kernel_launch(void* const* d_in, const int* in_sizes, int n_in,
                              void* d_out, int out_size) {
    const float* features = (const float*)d_in[0];
    const int*   ei       = (const int*)d_in[1];
    const float* W0 = (const float*)d_in[2];
    const float* b0 = (const float*)d_in[3];
    const float* W1 = (const float*)d_in[4];
    const float* b1 = (const float*)d_in[5];
    const float* W2 = (const float*)d_in[6];
    const float* b2 = (const float*)d_in[7];
    const float* W3 = (const float*)d_in[8];
    const float* b3 = (const float*)d_in[9];
    float* out = (float*)d_out;

    const int TB = 256;
    int nBlocksN = (NN + TB - 1) / TB;
    int nBlocksE = (EE + TB - 1) / TB;
    int nbScan   = (NN + 1023) / 1024;

    const int SMEM128 = 65536 + 128 * 256 * 2;   // 131072
    const int SMEM64  = 65536 + 64  * 256 * 2;   //  98304
    cudaFuncSetAttribute(gemm_mma_kernel<128, true, true>,
                         cudaFuncAttributeMaxDynamicSharedMemorySize, SMEM128);
    cudaFuncSetAttribute(gemm_mma_kernel<128, false, true>,
                         cudaFuncAttributeMaxDynamicSharedMemorySize, SMEM128);
    cudaFuncSetAttribute(gemm_mma_kernel<64, false, false>,
                         cudaFuncAttributeMaxDynamicSharedMemorySize, SMEM64);

    // ---- graph preprocessing (CSR by dst) ----
    detect_kernel<<<1, 128>>>(ei);
    zero_kernel<<<nBlocksN, TB>>>();
    degree_kernel<<<nBlocksE, TB>>>(ei);
    norm_kernel<<<nBlocksN, TB>>>();
    scan1_kernel<<<nbScan, 1024>>>();
    scan2_kernel<<<1, 32>>>(nbScan);
    scan3_kernel<<<nBlocksN, TB>>>();
    fill_csr_kernel<<<nBlocksE, TB>>>(ei);

    const int GEMM_BLOCKS = 148;
    const int AGG_BLOCKS  = (NN * 32 + TB - 1) / TB;

    // layer 0 (fp16 h)
    gemm_mma_kernel<128, true, true><<<GEMM_BLOCKS, TB, SMEM128>>>(features, W0);
    aggregate_half_kernel<true><<<AGG_BLOCKS, TB>>>(b0);
    // layer 1 (fp16 h)
    gemm_mma_kernel<128, false, true><<<GEMM_BLOCKS, TB, SMEM128>>>(nullptr, W1);
    aggregate_half_kernel<true><<<AGG_BLOCKS, TB>>>(b1);
    // layer 2 (fp16 h)
    gemm_mma_kernel<128, false, true><<<GEMM_BLOCKS, TB, SMEM128>>>(nullptr, W2);
    aggregate_half_kernel<true><<<AGG_BLOCKS, TB>>>(b2);
    // layer 3 (fp32 h, D_OUT=64, no activation) -> d_out
    gemm_mma_kernel<64, false, false><<<GEMM_BLOCKS, TB, SMEM64>>>(nullptr, W3);
    aggregate64_kernel<<<AGG_BLOCKS, TB>>>(b3, out);
}